// round 1
// baseline (speedup 1.0000x reference)
#include <cuda_runtime.h>

#define BB 4
#define DD 4
#define HH 768
#define WW 768

// Each thread computes 4 consecutive w voxels (float4 I/O).
// Block = 192 threads = one full H-row of one (b,d) plane.
// Grid = B*D*H = 12288 blocks.
__global__ __launch_bounds__(192)
void cqi3d_kernel(const float* __restrict__ x, float* __restrict__ out) {
    const int w0 = threadIdx.x * 4;
    const int h  = blockIdx.x % HH;
    const int p  = blockIdx.x / HH;   // 0..15
    const int d  = p % DD;
    const int b  = p / DD;

    const int wl = (w0 == 0) ? 0 : (w0 - 1);
    const int wr = (w0 + 4 >= WW) ? (WW - 1) : (w0 + 4);

    // v[dd][hh][k]: k=0 -> w0-1 (clamped), k=1..4 -> w0..w0+3, k=5 -> w0+4 (clamped)
    float v[3][3][6];

    #pragma unroll
    for (int dd = 0; dd < 3; dd++) {
        int dc = d + dd - 1;
        dc = dc < 0 ? 0 : (dc >= DD ? DD - 1 : dc);
        const float* plane = x + ((size_t)(b * DD + dc) * HH) * WW;
        #pragma unroll
        for (int hh = 0; hh < 3; hh++) {
            int hc = h + hh - 1;
            hc = hc < 0 ? 0 : (hc >= HH ? HH - 1 : hc);
            const float* row = plane + (size_t)hc * WW;
            float4 c4 = *reinterpret_cast<const float4*>(row + w0);
            v[dd][hh][0] = __ldg(row + wl);
            v[dd][hh][1] = c4.x;
            v[dd][hh][2] = c4.y;
            v[dd][hh][3] = c4.z;
            v[dd][hh][4] = c4.w;
            v[dd][hh][5] = __ldg(row + wr);
        }
    }

    // Separable NMS column maxima:
    // m8[k] = max over the 8 (dd,hh) != (1,1) at w-index k
    // m9[k] = max over all 9 (dd,hh) at w-index k
    float m8[6], m9[6];
    #pragma unroll
    for (int k = 0; k < 6; k++) {
        float a = fmaxf(fmaxf(v[0][0][k], v[0][1][k]), fmaxf(v[0][2][k], v[1][0][k]));
        float bq = fmaxf(fmaxf(v[1][2][k], v[2][0][k]), fmaxf(v[2][1][k], v[2][2][k]));
        m8[k] = fmaxf(a, bq);
        m9[k] = fmaxf(m8[k], v[1][1][k]);
    }

    float oc0[4], oc1[4], oc2[4], oy[4];

    #pragma unroll
    for (int j = 0; j < 4; j++) {
        const int c = j + 1;
        const float x0  = v[1][1][c];
        const float xl2 = v[1][1][c - 1], xr2 = v[1][1][c + 1];
        const float yl  = v[1][0][c],     yr  = v[1][2][c];
        const float sl2 = v[0][1][c],     sr2 = v[2][1][c];

        const float gx = 0.5f * (xr2 - xl2);
        const float gy = 0.5f * (yr - yl);
        const float gs = 0.5f * (sr2 - sl2);

        const float dxx = xr2 - 2.0f * x0 + xl2;
        const float dyy = yr  - 2.0f * x0 + yl;
        const float dss = sr2 - 2.0f * x0 + sl2;

        const float dxy =  0.25f * (v[1][2][c + 1] - v[1][2][c - 1] - v[1][0][c + 1] + v[1][0][c - 1]);
        const float dys = -0.25f * (v[2][2][c]     - v[2][0][c]     - v[0][2][c]     + v[0][0][c]);
        const float dxs = -0.25f * (v[2][1][c + 1] - v[2][1][c - 1] - v[0][1][c + 1] + v[0][1][c - 1]);

        // NMS: strict max over 26 neighbors and > 0 (zeroed-center kernel channel)
        const float nbmax = fmaxf(fmaxf(m9[j], m9[j + 2]), fmaxf(m8[j + 1], 0.0f));
        const bool nms = (x0 > nbmax);

        // Cramer solve H s = g (symmetric 3x3)
        const float cf00 = dyy * dss - dys * dys;
        const float cf01 = dxy * dss - dys * dxs;
        const float cf02 = dxy * dys - dyy * dxs;
        const float det  = dxx * cf00 - dxy * cf01 + dxs * cf02;
        const bool solved = (det != 0.0f);
        const float sdet = solved ? det : 1.0f;
        const float inv = 1.0f / sdet;

        const float t0 = gy * dss - dys * gs;   // r1*dss - dys*r2
        const float t1 = gy * dys - dyy * gs;   // r1*dys - dyy*r2
        const float t2 = dxy * gs - gy * dxs;   // dxy*r2 - r1*dxs

        const float sx = (gx  * cf00 - dxy * t0 + dxs * t1) * inv;
        const float sy = (dxx * t0   - gx  * cf01 + dxs * t2) * inv;
        const float ss = (-dxx * t1  - dxy * t2 + gx * cf02) * inv;

        const bool valid = nms && solved;
        float dx_x = valid ? -sx : 0.0f;
        float dx_y = valid ? -sy : 0.0f;
        float dx_s = valid ? -ss : 0.0f;

        const bool big = fmaxf(fmaxf(fabsf(dx_x), fabsf(dx_y)), fabsf(dx_s)) > 0.7f;
        if (big) { dx_x = 0.0f; dx_y = 0.0f; dx_s = 0.0f; }

        const float dyv = 0.5f * (gx * dx_x + gy * dx_y + gs * dx_s);
        const float ym = x0 + dyv + (valid ? 10.0f : 0.0f);

        oc0[j] = (float)d + dx_s;           // channel 0: zz + dx_s
        oc1[j] = (float)(w0 + j) + dx_x;    // channel 1: xx + dx_x
        oc2[j] = (float)h + dx_y;           // channel 2: yy + dx_y
        oy[j]  = ym;
    }

    const size_t HW = (size_t)HH * WW;
    const size_t sp = (size_t)h * WW + w0;

    float4* p0 = reinterpret_cast<float4*>(out + ((size_t)(b * 3 + 0) * DD + d) * HW + sp);
    float4* p1 = reinterpret_cast<float4*>(out + ((size_t)(b * 3 + 1) * DD + d) * HW + sp);
    float4* p2 = reinterpret_cast<float4*>(out + ((size_t)(b * 3 + 2) * DD + d) * HW + sp);
    float4* py = reinterpret_cast<float4*>(out + (size_t)3 * BB * DD * HW + ((size_t)(b * DD + d)) * HW + sp);

    *p0 = make_float4(oc0[0], oc0[1], oc0[2], oc0[3]);
    *p1 = make_float4(oc1[0], oc1[1], oc1[2], oc1[3]);
    *p2 = make_float4(oc2[0], oc2[1], oc2[2], oc2[3]);
    *py = make_float4(oy[0],  oy[1],  oy[2],  oy[3]);
}

extern "C" void kernel_launch(void* const* d_in, const int* in_sizes, int n_in,
                              void* d_out, int out_size) {
    const float* x = (const float*)d_in[0];
    float* out = (float*)d_out;
    dim3 grid(BB * DD * HH);   // 12288 blocks, one H-row each
    dim3 block(WW / 4);        // 192 threads
    cqi3d_kernel<<<grid, block>>>(x, out);
}

// round 2
// speedup vs baseline: 1.1388x; 1.1388x over previous
#include <cuda_runtime.h>

#define BB 4
#define DD 4
#define HH 768
#define WW 768
#define RR 4   // output rows per block

// Load one padded row segment of 6 values: [w0-1, w0..w0+3, w0+4].
// Halo via warp shuffle; lanes 0/31 use predicated scalar loads.
__device__ __forceinline__ void load_row6(const float* __restrict__ row, int w0, int lane,
                                          float v[6]) {
    float4 c4 = *reinterpret_cast<const float4*>(row + w0);
    float lv = __shfl_up_sync(0xffffffffu, c4.w, 1);
    float rv = __shfl_down_sync(0xffffffffu, c4.x, 1);
    if (lane == 0) {
        const int wl = (w0 == 0) ? 0 : (w0 - 1);
        lv = __ldg(row + wl);
    }
    if (lane == 31) {
        const int wr = (w0 + 4 >= WW) ? (WW - 1) : (w0 + 4);
        rv = __ldg(row + wr);
    }
    v[0] = lv; v[1] = c4.x; v[2] = c4.y; v[3] = c4.z; v[4] = c4.w; v[5] = rv;
}

// Block = 192 threads = one full W row (192*4 = 768).
// Each block produces RR consecutive h rows of one (b,d) plane, sliding a
// 3-slot register window down h. Grid = B*D*(H/RR) = 3072 blocks.
__global__ __launch_bounds__(192)
void cqi3d_kernel(const float* __restrict__ x, float* __restrict__ out) {
    const int tid  = threadIdx.x;
    const int lane = tid & 31;
    const int w0   = tid * 4;
    const int hb   = (blockIdx.x % (HH / RR)) * RR;
    const int p    = blockIdx.x / (HH / RR);
    const int d    = p % DD;
    const int b    = p / DD;

    const int dm = (d == 0) ? 0 : d - 1;
    const int dp = (d == DD - 1) ? (DD - 1) : d + 1;
    const float* pl0 = x + ((size_t)(b * DD + dm) * HH) * WW;  // d-1 plane
    const float* pl1 = x + ((size_t)(b * DD + d ) * HH) * WW;  // d   plane
    const float* pl2 = x + ((size_t)(b * DD + dp) * HH) * WW;  // d+1 plane

    // v[dd][slot][k]: sliding window, slot role rotates (st/sm/sb).
    float v[3][3][6];
    // rm9[slot][k] = max over dd of v[dd][slot][k]  (for NMS)
    float rm9[3][6];

    // ---- prologue: slot 0 = row hb-1 (clamped), slot 1 = row hb ----
    {
        const int ht = (hb == 0) ? 0 : (hb - 1);
        load_row6(pl0 + (size_t)ht * WW, w0, lane, v[0][0]);
        load_row6(pl1 + (size_t)ht * WW, w0, lane, v[1][0]);
        load_row6(pl2 + (size_t)ht * WW, w0, lane, v[2][0]);
        load_row6(pl0 + (size_t)hb * WW, w0, lane, v[0][1]);
        load_row6(pl1 + (size_t)hb * WW, w0, lane, v[1][1]);
        load_row6(pl2 + (size_t)hb * WW, w0, lane, v[2][1]);
        #pragma unroll
        for (int k = 0; k < 6; k++) {
            rm9[0][k] = fmaxf(fmaxf(v[0][0][k], v[1][0][k]), v[2][0][k]);
            rm9[1][k] = fmaxf(fmaxf(v[0][1][k], v[1][1][k]), v[2][1][k]);
        }
    }

    const size_t HW = (size_t)HH * WW;
    const size_t sp = (size_t)hb * WW + w0;
    float* o0 = out + ((size_t)(b * 3 + 0) * DD + d) * HW + sp;                 // zz + dx_s
    float* o1 = out + ((size_t)(b * 3 + 1) * DD + d) * HW + sp;                 // xx + dx_x
    float* o2 = out + ((size_t)(b * 3 + 2) * DD + d) * HW + sp;                 // yy + dx_y
    float* oy = out + (size_t)3 * BB * DD * HW + ((size_t)(b * DD + d)) * HW + sp;

    #pragma unroll
    for (int r = 0; r < RR; r++) {
        const int st = r % 3;        // slot holding row h-1
        const int sm = (r + 1) % 3;  // slot holding row h
        const int sb = (r + 2) % 3;  // slot to fill with row h+1
        const int h  = hb + r;

        // ---- load next row (h+1, clamped) into slot sb ----
        {
            const int hn = (h + 1 >= HH) ? (HH - 1) : (h + 1);
            load_row6(pl0 + (size_t)hn * WW, w0, lane, v[0][sb]);
            load_row6(pl1 + (size_t)hn * WW, w0, lane, v[1][sb]);
            load_row6(pl2 + (size_t)hn * WW, w0, lane, v[2][sb]);
            #pragma unroll
            for (int k = 0; k < 6; k++)
                rm9[sb][k] = fmaxf(fmaxf(v[0][sb][k], v[1][sb][k]), v[2][sb][k]);
        }

        float oc0[4], oc1[4], oc2[4], oyv[4];

        #pragma unroll
        for (int j = 0; j < 4; j++) {
            const int c = j + 1;
            const float x0  = v[1][sm][c];
            const float xl2 = v[1][sm][c - 1], xr2 = v[1][sm][c + 1];
            const float yl  = v[1][st][c],     yr  = v[1][sb][c];
            const float sl2 = v[0][sm][c],     sr2 = v[2][sm][c];

            const float gx = 0.5f * (xr2 - xl2);
            const float gy = 0.5f * (yr - yl);
            const float gs = 0.5f * (sr2 - sl2);

            const float dxx = xr2 - 2.0f * x0 + xl2;
            const float dyy = yr  - 2.0f * x0 + yl;
            const float dss = sr2 - 2.0f * x0 + sl2;

            const float dxy =  0.25f * (v[1][sb][c + 1] - v[1][sb][c - 1] - v[1][st][c + 1] + v[1][st][c - 1]);
            const float dys = -0.25f * (v[2][sb][c]     - v[2][st][c]     - v[0][sb][c]     + v[0][st][c]);
            const float dxs = -0.25f * (v[2][sm][c + 1] - v[2][sm][c - 1] - v[0][sm][c + 1] + v[0][sm][c - 1]);

            // NMS: strict max over 26 neighbours AND > 0
            float nb = fmaxf(rm9[st][c - 1], rm9[st][c]);
            nb = fmaxf(nb, rm9[st][c + 1]);
            nb = fmaxf(nb, rm9[sb][c - 1]);
            nb = fmaxf(nb, rm9[sb][c]);
            nb = fmaxf(nb, rm9[sb][c + 1]);
            nb = fmaxf(nb, rm9[sm][c - 1]);
            nb = fmaxf(nb, rm9[sm][c + 1]);
            nb = fmaxf(nb, fmaxf(sl2, sr2));   // middle row, center col: dd != 1 only
            nb = fmaxf(nb, 0.0f);
            const bool nms = (x0 > nb);

            // Cramer solve H s = g (symmetric 3x3)
            const float cf00 = dyy * dss - dys * dys;
            const float cf01 = dxy * dss - dys * dxs;
            const float cf02 = dxy * dys - dyy * dxs;
            const float det  = dxx * cf00 - dxy * cf01 + dxs * cf02;
            const bool solved = (det != 0.0f);
            const float inv = 1.0f / (solved ? det : 1.0f);

            const float t0 = gy * dss - dys * gs;
            const float t1 = gy * dys - dyy * gs;
            const float t2 = dxy * gs - gy * dxs;

            const float sx = (gx  * cf00 - dxy * t0   + dxs * t1) * inv;
            const float sy = (dxx * t0   - gx  * cf01 + dxs * t2) * inv;
            const float ss = (-dxx * t1  - dxy * t2   + gx  * cf02) * inv;

            const bool valid = nms && solved;
            float dx_x = valid ? -sx : 0.0f;
            float dx_y = valid ? -sy : 0.0f;
            float dx_s = valid ? -ss : 0.0f;

            const bool big = fmaxf(fmaxf(fabsf(dx_x), fabsf(dx_y)), fabsf(dx_s)) > 0.7f;
            if (big) { dx_x = 0.0f; dx_y = 0.0f; dx_s = 0.0f; }

            const float dyv = 0.5f * (gx * dx_x + gy * dx_y + gs * dx_s);

            oc0[j] = (float)d + dx_s;
            oc1[j] = (float)(w0 + j) + dx_x;
            oc2[j] = (float)h + dx_y;
            oyv[j] = x0 + dyv + (valid ? 10.0f : 0.0f);
        }

        *reinterpret_cast<float4*>(o0 + (size_t)r * WW) = make_float4(oc0[0], oc0[1], oc0[2], oc0[3]);
        *reinterpret_cast<float4*>(o1 + (size_t)r * WW) = make_float4(oc1[0], oc1[1], oc1[2], oc1[3]);
        *reinterpret_cast<float4*>(o2 + (size_t)r * WW) = make_float4(oc2[0], oc2[1], oc2[2], oc2[3]);
        *reinterpret_cast<float4*>(oy + (size_t)r * WW) = make_float4(oyv[0], oyv[1], oyv[2], oyv[3]);
    }
}

extern "C" void kernel_launch(void* const* d_in, const int* in_sizes, int n_in,
                              void* d_out, int out_size) {
    const float* x = (const float*)d_in[0];
    float* out = (float*)d_out;
    dim3 grid(BB * DD * (HH / RR));  // 3072 blocks
    dim3 block(192);                 // one full W row per block
    cqi3d_kernel<<<grid, block>>>(x, out);
}

// round 4
// speedup vs baseline: 1.1805x; 1.0366x over previous
#include <cuda_runtime.h>

#define BB 4
#define DD 4
#define HH 768
#define WW 768
#define RR 4   // output rows per block

// Load one padded row segment of 6 values: [w0-1, w0..w0+3, w0+4].
// Halo via warp shuffle; lanes 0/31 use predicated scalar loads.
__device__ __forceinline__ void load_row6(const float* __restrict__ row, int w0, int lane,
                                          float v[6]) {
    float4 c4 = *reinterpret_cast<const float4*>(row + w0);
    float lv = __shfl_up_sync(0xffffffffu, c4.w, 1);
    float rv = __shfl_down_sync(0xffffffffu, c4.x, 1);
    if (lane == 0) {
        const int wl = (w0 == 0) ? 0 : (w0 - 1);
        lv = __ldg(row + wl);
    }
    if (lane == 31) {
        const int wr = (w0 + 4 >= WW) ? (WW - 1) : (w0 + 4);
        rv = __ldg(row + wr);
    }
    v[0] = lv; v[1] = c4.x; v[2] = c4.y; v[3] = c4.z; v[4] = c4.w; v[5] = rv;
}

// Block = 192 threads = one full W row (192*4 = 768).
// Each block produces RR consecutive h rows of one (b,d) plane, sliding a
// 3-slot register window down h. Grid = B*D*(H/RR) = 3072 blocks.
__global__ __launch_bounds__(192, 4)
void cqi3d_kernel(const float* __restrict__ x, float* __restrict__ out) {
    const int tid  = threadIdx.x;
    const int lane = tid & 31;
    const int w0   = tid * 4;
    const int hb   = (blockIdx.x % (HH / RR)) * RR;
    const int p    = blockIdx.x / (HH / RR);
    const int d    = p % DD;
    const int b    = p / DD;

    const int dm = (d == 0) ? 0 : d - 1;
    const int dp = (d == DD - 1) ? (DD - 1) : d + 1;
    const float* pl0 = x + ((size_t)(b * DD + dm) * HH) * WW;  // d-1 plane
    const float* pl1 = x + ((size_t)(b * DD + d ) * HH) * WW;  // d   plane
    const float* pl2 = x + ((size_t)(b * DD + dp) * HH) * WW;  // d+1 plane

    // v[dd][slot][k]: sliding window, slot role rotates (st/sm/sb).
    float v[3][3][6];
    // rm9[slot][k] = max over dd of v[dd][slot][k]  (for NMS)
    float rm9[3][6];

    // ---- prologue: slot 0 = row hb-1 (clamped), slot 1 = row hb ----
    {
        const int ht = (hb == 0) ? 0 : (hb - 1);
        load_row6(pl0 + (size_t)ht * WW, w0, lane, v[0][0]);
        load_row6(pl1 + (size_t)ht * WW, w0, lane, v[1][0]);
        load_row6(pl2 + (size_t)ht * WW, w0, lane, v[2][0]);
        load_row6(pl0 + (size_t)hb * WW, w0, lane, v[0][1]);
        load_row6(pl1 + (size_t)hb * WW, w0, lane, v[1][1]);
        load_row6(pl2 + (size_t)hb * WW, w0, lane, v[2][1]);
        #pragma unroll
        for (int k = 0; k < 6; k++) {
            rm9[0][k] = fmaxf(fmaxf(v[0][0][k], v[1][0][k]), v[2][0][k]);
            rm9[1][k] = fmaxf(fmaxf(v[0][1][k], v[1][1][k]), v[2][1][k]);
        }
    }

    const size_t HW = (size_t)HH * WW;
    const size_t sp = (size_t)hb * WW + w0;
    float* o0 = out + ((size_t)(b * 3 + 0) * DD + d) * HW + sp;                 // zz + dx_s
    float* o1 = out + ((size_t)(b * 3 + 1) * DD + d) * HW + sp;                 // xx + dx_x
    float* o2 = out + ((size_t)(b * 3 + 2) * DD + d) * HW + sp;                 // yy + dx_y
    float* oy = out + (size_t)3 * BB * DD * HW + ((size_t)(b * DD + d)) * HW + sp;

    #pragma unroll
    for (int r = 0; r < RR; r++) {
        const int st = r % 3;        // slot holding row h-1
        const int sm = (r + 1) % 3;  // slot holding row h
        const int sb = (r + 2) % 3;  // slot to fill with row h+1
        const int h  = hb + r;

        // ---- load next row (h+1, clamped) into slot sb ----
        {
            const int hn = (h + 1 >= HH) ? (HH - 1) : (h + 1);
            load_row6(pl0 + (size_t)hn * WW, w0, lane, v[0][sb]);
            load_row6(pl1 + (size_t)hn * WW, w0, lane, v[1][sb]);
            load_row6(pl2 + (size_t)hn * WW, w0, lane, v[2][sb]);
            #pragma unroll
            for (int k = 0; k < 6; k++)
                rm9[sb][k] = fmaxf(fmaxf(v[0][sb][k], v[1][sb][k]), v[2][sb][k]);
        }

        float oc0[4], oc1[4], oc2[4], oyv[4];

        #pragma unroll
        for (int j = 0; j < 4; j++) {
            const int c = j + 1;
            const float x0  = v[1][sm][c];
            const float xl2 = v[1][sm][c - 1], xr2 = v[1][sm][c + 1];
            const float yl  = v[1][st][c],     yr  = v[1][sb][c];
            const float sl2 = v[0][sm][c],     sr2 = v[2][sm][c];

            const float gx = 0.5f * (xr2 - xl2);
            const float gy = 0.5f * (yr - yl);
            const float gs = 0.5f * (sr2 - sl2);

            const float dxx = xr2 - 2.0f * x0 + xl2;
            const float dyy = yr  - 2.0f * x0 + yl;
            const float dss = sr2 - 2.0f * x0 + sl2;

            const float dxy =  0.25f * (v[1][sb][c + 1] - v[1][sb][c - 1] - v[1][st][c + 1] + v[1][st][c - 1]);
            const float dys = -0.25f * (v[2][sb][c]     - v[2][st][c]     - v[0][sb][c]     + v[0][st][c]);
            const float dxs = -0.25f * (v[2][sm][c + 1] - v[2][sm][c - 1] - v[0][sm][c + 1] + v[0][sm][c - 1]);

            // NMS: strict max over 26 neighbours AND > 0
            float nb = fmaxf(rm9[st][c - 1], rm9[st][c]);
            nb = fmaxf(nb, rm9[st][c + 1]);
            nb = fmaxf(nb, rm9[sb][c - 1]);
            nb = fmaxf(nb, rm9[sb][c]);
            nb = fmaxf(nb, rm9[sb][c + 1]);
            nb = fmaxf(nb, rm9[sm][c - 1]);
            nb = fmaxf(nb, rm9[sm][c + 1]);
            nb = fmaxf(nb, fmaxf(sl2, sr2));   // middle row, center col: dd != 1 only
            nb = fmaxf(nb, 0.0f);
            const bool nms = (x0 > nb);

            // Cramer solve H s = g (symmetric 3x3)
            const float cf00 = dyy * dss - dys * dys;
            const float cf01 = dxy * dss - dys * dxs;
            const float cf02 = dxy * dys - dyy * dxs;
            const float det  = dxx * cf00 - dxy * cf01 + dxs * cf02;
            const bool solved = (det != 0.0f);
            const float sdet = solved ? det : 1.0f;
            float inv;
            asm("rcp.approx.f32 %0, %1;" : "=f"(inv) : "f"(sdet));

            const float t0 = gy * dss - dys * gs;
            const float t1 = gy * dys - dyy * gs;
            const float t2 = dxy * gs - gy * dxs;

            const float sx = (gx  * cf00 - dxy * t0   + dxs * t1) * inv;
            const float sy = (dxx * t0   - gx  * cf01 + dxs * t2) * inv;
            const float ss = (-dxx * t1  - dxy * t2   + gx  * cf02) * inv;

            const bool valid = nms && solved;
            // reject if any |offset| > 0.7 (offset = -s); fold with valid
            const float amax = fmaxf(fmaxf(fabsf(sx), fabsf(sy)), fabsf(ss));
            const bool keep = valid && (amax <= 0.7f);

            const float dx_x = keep ? -sx : 0.0f;
            const float dx_y = keep ? -sy : 0.0f;
            const float dx_s = keep ? -ss : 0.0f;

            // dy = 0.5 * (gx*dx_x + gy*dx_y + gs*dx_s); bonus applies on valid alone
            float ym = valid ? (x0 + 10.0f) : x0;
            if (keep) {
                const float t = fmaf(gx, sx, fmaf(gy, sy, gs * ss));
                ym = fmaf(-0.5f, t, ym);
            }

            oc0[j] = (float)d + dx_s;
            oc1[j] = (float)(w0 + j) + dx_x;
            oc2[j] = (float)h + dx_y;
            oyv[j] = ym;
        }

        *reinterpret_cast<float4*>(o0 + (size_t)r * WW) = make_float4(oc0[0], oc0[1], oc0[2], oc0[3]);
        *reinterpret_cast<float4*>(o1 + (size_t)r * WW) = make_float4(oc1[0], oc1[1], oc1[2], oc1[3]);
        *reinterpret_cast<float4*>(o2 + (size_t)r * WW) = make_float4(oc2[0], oc2[1], oc2[2], oc2[3]);
        *reinterpret_cast<float4*>(oy + (size_t)r * WW) = make_float4(oyv[0], oyv[1], oyv[2], oyv[3]);
    }
}

extern "C" void kernel_launch(void* const* d_in, const int* in_sizes, int n_in,
                              void* d_out, int out_size) {
    const float* x = (const float*)d_in[0];
    float* out = (float*)d_out;
    dim3 grid(BB * DD * (HH / RR));  // 3072 blocks
    dim3 block(192);                 // one full W row per block
    cqi3d_kernel<<<grid, block>>>(x, out);
}